// round 3
// baseline (speedup 1.0000x reference)
#include <cuda_runtime.h>
#include <cstdint>

// MeanAggregator: out[b, :] = (1/K) * sum_k features[neigh_idx[b,k], :]
// features: [1e6, 128] fp32 (512 MB), neigh_idx: [1e5, 10] int32, out: [1e5,128] fp32.
//
// DRAM-bound gather. One warp handles TWO output rows:
//  - lane l owns float4 chunk l of the 512B row -> every gathered row is one
//    fully coalesced 512B access
//  - the 20 indices of rows (2w, 2w+1) are contiguous -> single coalesced
//    80B index load by lanes 0..19, broadcast via shfl
//  - 20 independent LDG.128 in flight per warp (MLP=20) hides DRAM latency
//  - output stored with __stcs (evict-first) so the 51 MB of writes don't
//    evict feature rows from L2 (more repeat-gather hits)

#define D 128
#define KNEIGH 10

__global__ __launch_bounds__(256) void mean_agg_kernel(
    const float* __restrict__ features,
    const int* __restrict__ neigh_idx,
    float* __restrict__ out,
    int B)
{
    const int warp_global = (blockIdx.x * blockDim.x + threadIdx.x) >> 5;
    const int lane = threadIdx.x & 31;

    const int b0 = warp_global * 2;
    const int b1 = b0 + 1;
    if (b0 >= B) return;
    const bool has_b1 = (b1 < B);

    // Lanes 0..19 load the 20 contiguous indices for rows b0, b1.
    int my_idx = 0;
    {
        const int nidx = has_b1 ? 2 * KNEIGH : KNEIGH;
        if (lane < nidx) {
            my_idx = neigh_idx[(long long)b0 * KNEIGH + lane];
        }
    }

    float4 acc0 = make_float4(0.f, 0.f, 0.f, 0.f);
    float4 acc1 = make_float4(0.f, 0.f, 0.f, 0.f);

    if (has_b1) {
        #pragma unroll
        for (int k = 0; k < KNEIGH; ++k) {
            long long j0 = __shfl_sync(0xffffffffu, my_idx, k);
            long long j1 = __shfl_sync(0xffffffffu, my_idx, k + KNEIGH);
            float4 v0 = reinterpret_cast<const float4*>(features + j0 * D)[lane];
            float4 v1 = reinterpret_cast<const float4*>(features + j1 * D)[lane];
            acc0.x += v0.x; acc0.y += v0.y; acc0.z += v0.z; acc0.w += v0.w;
            acc1.x += v1.x; acc1.y += v1.y; acc1.z += v1.z; acc1.w += v1.w;
        }
    } else {
        #pragma unroll
        for (int k = 0; k < KNEIGH; ++k) {
            long long j0 = __shfl_sync(0xffffffffu, my_idx, k);
            float4 v0 = reinterpret_cast<const float4*>(features + j0 * D)[lane];
            acc0.x += v0.x; acc0.y += v0.y; acc0.z += v0.z; acc0.w += v0.w;
        }
    }

    const float inv_k = 1.0f / (float)KNEIGH;
    float4 r0 = make_float4(acc0.x * inv_k, acc0.y * inv_k, acc0.z * inv_k, acc0.w * inv_k);
    __stcs(reinterpret_cast<float4*>(out + (long long)b0 * D) + lane, r0);
    if (has_b1) {
        float4 r1 = make_float4(acc1.x * inv_k, acc1.y * inv_k, acc1.z * inv_k, acc1.w * inv_k);
        __stcs(reinterpret_cast<float4*>(out + (long long)b1 * D) + lane, r1);
    }
}

extern "C" void kernel_launch(void* const* d_in, const int* in_sizes, int n_in,
                              void* d_out, int out_size)
{
    const float* features = (const float*)d_in[0];
    const int* neigh_idx  = (const int*)d_in[1];
    float* out            = (float*)d_out;

    const int B = in_sizes[1] / KNEIGH;   // 100,000

    const int rows_per_warp = 2;
    const int warps_per_block = 256 / 32; // 8
    const int rows_per_block = rows_per_warp * warps_per_block; // 16
    const int grid = (B + rows_per_block - 1) / rows_per_block; // 6,250

    mean_agg_kernel<<<grid, 256>>>(features, neigh_idx, out, B);
}

// round 5
// speedup vs baseline: 1.0269x; 1.0269x over previous
#include <cuda_runtime.h>
#include <cstdint>

// MeanAggregator: out[b, :] = (1/K) * sum_k features[neigh_idx[b,k], :]
// features: [1e6, 128] fp32 (512 MB), neigh_idx: [1e5, 10] int32, out: [1e5,128] fp32.
//
// R2 shape (one warp per output row; lane l owns float4 chunk l -> one fully
// coalesced 512B access per gathered row; K=10 fully unrolled -> MLP~10).
// L2 policy via createpolicy + cache_hint (the direct .L2::evict_last ld
// modifier is restricted to 256-bit forms on this ptxas):
//   - gathers:  evict_last  (feature rows are the only reusable data)
//   - stores:   __stcs      (touch-once output, evict-first)

#define D 128
#define KNEIGH 10

__device__ __forceinline__ float4 ldg_evict_last(const float4* p, uint64_t policy) {
    float4 v;
    asm volatile("ld.global.nc.L2::cache_hint.v4.f32 {%0,%1,%2,%3}, [%4], %5;"
                 : "=f"(v.x), "=f"(v.y), "=f"(v.z), "=f"(v.w)
                 : "l"(p), "l"(policy));
    return v;
}

__global__ __launch_bounds__(256) void mean_agg_kernel(
    const float* __restrict__ features,
    const int* __restrict__ neigh_idx,
    float* __restrict__ out,
    int B)
{
    const int warp_global = (blockIdx.x * blockDim.x + threadIdx.x) >> 5;
    const int lane = threadIdx.x & 31;
    if (warp_global >= B) return;

    uint64_t policy;
    asm("createpolicy.fractional.L2::evict_last.b64 %0, 1.0;" : "=l"(policy));

    // Lanes 0..9 each load one neighbor index for this row, broadcast via shfl.
    int my_idx = 0;
    if (lane < KNEIGH) {
        my_idx = neigh_idx[(long long)warp_global * KNEIGH + lane];
    }

    float4 acc = make_float4(0.f, 0.f, 0.f, 0.f);

    #pragma unroll
    for (int k = 0; k < KNEIGH; ++k) {
        long long j = __shfl_sync(0xffffffffu, my_idx, k);
        float4 v = ldg_evict_last(
            reinterpret_cast<const float4*>(features + j * D) + lane, policy);
        acc.x += v.x;
        acc.y += v.y;
        acc.z += v.z;
        acc.w += v.w;
    }

    const float inv_k = 1.0f / (float)KNEIGH;
    float4 r = make_float4(acc.x * inv_k, acc.y * inv_k, acc.z * inv_k, acc.w * inv_k);
    __stcs(reinterpret_cast<float4*>(out + (long long)warp_global * D) + lane, r);
}

extern "C" void kernel_launch(void* const* d_in, const int* in_sizes, int n_in,
                              void* d_out, int out_size)
{
    const float* features = (const float*)d_in[0];
    const int* neigh_idx  = (const int*)d_in[1];
    float* out            = (float*)d_out;

    const int B = in_sizes[1] / KNEIGH;   // 100,000

    const int warps_per_block = 256 / 32; // 8
    const int grid = (B + warps_per_block - 1) / warps_per_block; // 12,500

    mean_agg_kernel<<<grid, 256>>>(features, neigh_idx, out, B);
}